// round 13
// baseline (speedup 1.0000x reference)
#include <cuda_runtime.h>

constexpr int kB = 32;
constexpr int kA = 5;
constexpr int kC = 8;
constexpr int kH = 32;
constexpr int kW = 64;
constexpr int kT = 50;
constexpr int kCh = 7 + kC;                 // 15
constexpr int kHW = kH * kW;                // 2048
constexpr int kThreads = 512;               // 1 cell/thread: anchor x 8 rows x 64 cols
constexpr int kBlocksPerB = 20;             // 10240 / 512
constexpr int kGrid = kB * kBlocksPerB;     // 640

__constant__ float c_aw[kA] = {1.08f, 3.42f, 6.63f, 9.42f, 16.62f};
__constant__ float c_al[kA] = {1.19f, 4.41f, 11.38f, 5.11f, 10.52f};

__device__ float        g_partials[kGrid];
__device__ unsigned int g_count = 0;   // self-resets -> graph-replay deterministic

__shared__ float4   cbox[kT];          // {x1, 1.6*y1, x2, 1.6*y2}
__shared__ float    cna[kT];           // -0.6 * target area
__shared__ float2   sxw[kT];           // x-window {txc - tw/3 - eps, txc + tw/3 + eps}
__shared__ float2   syw[kT];           // y-window {tyc - tl/3 - eps, tyc + tl/3 + eps}
__shared__ float    std_[kT][12];      // tx,ty,tw,tl,tim,tre,tcls, x1,y1s,x2,y2s
__shared__ int      s_map[kThreads];   // block-local cell -> winning target
__shared__ unsigned s_mask[2];
__shared__ int      s_cnt;
__shared__ float    wred[16];
__shared__ bool     s_last;

// matched-cell loss (rare: <=50 cells/batch; spills here are acceptable)
__device__ __forceinline__ float matched_loss(
    int map, const float* __restrict__ base,
    float sxv, float syv, float conf, float c2, float c3,
    float x1, float x2, float y1s, float y2s, float parea)
{
    float c4 = base[4 * kHW];
    float c5 = base[5 * kHW];
    float dx   = sxv - std_[map][0];
    float dy   = syv - std_[map][1];
    float dw   = c2  - std_[map][2];
    float dl   = c3  - std_[map][3];
    float dim_ = c4  - std_[map][4];
    float dre  = c5  - std_[map][5];

    float bx1 = std_[map][7], by1s = std_[map][8];
    float bx2 = std_[map][9], by2s = std_[map][10];
    float cw  = fminf(x2, bx2) - fmaxf(x1, bx1);
    float chs = fminf(y2s, by2s) - fmaxf(y1s, by1s);
    float inter = fmaxf(cw, 0.0f) * fmaxf(chs, 0.0f) * 0.625f;
    float tgw = bx2 - bx1;
    float tgl = (by2s - by1s) * 0.625f;
    float uni = parea + tgw * tgl - inter;
    float tconf = inter / uni;
    float dconf = conf * 10.0f - tconf * 10.0f;

    float cl[kC];
#pragma unroll
    for (int q = 0; q < kC; q++) cl[q] = base[(size_t)(7 + q) * kHW];
    float mx = cl[0];
#pragma unroll
    for (int q = 1; q < kC; q++) mx = fmaxf(mx, cl[q]);
    float s = 0.0f;
#pragma unroll
    for (int q = 0; q < kC; q++) s += __expf(cl[q] - mx);
    int tcls = (int)std_[map][6];
    float ce = mx + logf(s) - cl[tcls];

    return dx * dx + dy * dy + dw * dw + dl * dl + dim_ * dim_ + dre * dre
         + dconf * dconf + ce;
}

__global__ void __launch_bounds__(kThreads, 4) k_fused(const float* __restrict__ out,
                                                       const float* __restrict__ tgt,
                                                       float* __restrict__ loss,
                                                       int out_size) {
    const int tid = threadIdx.x;
    const int bid = blockIdx.x;
    const int b   = bid / kBlocksPerB;
    const int cb  = bid - b * kBlocksPerB;
    const int a   = cb >> 2;                       // anchor
    const int g8  = cb & 3;                        // 8-row group
    const int rowbase = g8 << 3;

    // warp tiling: 16 cols x 2 rows per warp; 1 cell/thread; 16 warps/block
    const int lane = tid & 31;
    const int wrp  = tid >> 5;                     // 0..15
    const int xT   = wrp & 3;                      // 0..3 (16-col tiles)
    const int yT   = wrp >> 2;                     // 0..3 (2-row tiles)
    const int i    = (xT << 4) + (lane & 15);      // 0..63
    const int jLoc = (yT << 1) + (lane >> 4);      // 0..7
    const int j    = rowbase + jLoc;
    const int off0 = (jLoc << 6) + i;              // s_map index
    const int rem  = (j << 6) + i;

    // hot channels (c4/c5 matched-path-only)
    const float* base = out + ((size_t)(b * kA + a) * kCh) * kHW + rem;
    float a0 = base[0 * kHW];
    float a1 = base[1 * kHW];
    float a2 = base[2 * kHW];
    float a3 = base[3 * kHW];
    float a6 = base[6 * kHW];

    // ---------------- phase 1: per-target values + masks --------------------
    s_map[tid] = -1;
    if (tid == 0) s_cnt = 0;

    const float* tr = tgt + ((size_t)b * kT + tid) * 7;
    bool validt = (tid < kT) && (tr[1] != 0.0f);
    unsigned bm = __ballot_sync(0xffffffffu, validt);
    if ((tid & 31) == 0 && tid < 64) s_mask[tid >> 5] = bm;

    float gx = 0.f, gy = 0.f, gw = 0.f, gl = 0.f, garea = 0.f;
    int gi = 0, gj = 0, besta = 0, off = -1;
    if (validt) {
        gx = tr[1] * (float)kW;
        gy = tr[2] * (float)kH;
        gw = tr[3] * (float)kW;
        gl = tr[4] * (float)kH;
        gi = min(max((int)gx, 0), kW - 1);
        gj = min(max((int)gy, 0), kH - 1);
        garea = gw * gl;

        // division-free first-max-wins anchor argmax
        float bin = fminf(gw, c_aw[0]) * fminf(gl, c_al[0]);
        float bun = garea + c_aw[0] * c_al[0] - bin;
#pragma unroll
        for (int q = 1; q < kA; q++) {
            float in_ = fminf(gw, c_aw[q]) * fminf(gl, c_al[q]);
            float un_ = garea + c_aw[q] * c_al[q] - in_;
            if (in_ * bun > bin * un_) { besta = q; bin = in_; bun = un_; }
        }
        if (besta == a && gj >= rowbase && gj < rowbase + 8)
            off = ((gj - rowbase) << 6) + gi;
    }
    __syncthreads();                               // sync 1

    unsigned long long mm = (unsigned long long)s_mask[0]
                          | ((unsigned long long)s_mask[1] << 32);
    const int nv = __ffsll((long long)~mm) - 1;    // cumprod-validity prefix

    const bool inpfx = (tid < nv);
    if (inpfx) {
        if (off >= 0) atomicMax(&s_map[off], tid);
        // block-level y-cull over 8 rows: IoU>0.6 needs |pyc-tyc| < tl/3
        float tl3 = gl * (1.0f / 3.0f) + 1e-3f;
        float tw3 = gw * (1.0f / 3.0f) + 1e-3f;
        if (gy + tl3 > (float)rowbase && gy - tl3 < (float)(rowbase + 8)) {
            int p = atomicAdd(&s_cnt, 1);
            cbox[p] = make_float4(gx - gw * 0.5f, 1.6f * (gy - gl * 0.5f),
                                  gx + gw * 0.5f, 1.6f * (gy + gl * 0.5f));
            cna[p]  = -0.6f * garea;
            sxw[p] = make_float2(gx - tw3, gx + tw3);
            syw[p] = make_float2(gy - tl3, gy + tl3);
        }
    }
    __syncthreads();                               // sync 2

    // phase 2: dedupe winners write regression targets (hidden behind loop)
    if (inpfx && off >= 0 && s_map[off] == tid) {
        std_[tid][0] = gx - (float)gi;
        std_[tid][1] = gy - (float)gj;
        std_[tid][2] = logf(gw / c_aw[besta]);
        std_[tid][3] = logf(gl / c_al[besta]);
        std_[tid][4] = tr[5];
        std_[tid][5] = tr[6];
        std_[tid][6] = tr[0];
        std_[tid][7] = gx - gw * 0.5f;
        std_[tid][8] = 1.6f * (gy - gl * 0.5f);
        std_[tid][9] = gx + gw * 0.5f;
        std_[tid][10] = 1.6f * (gy + gl * 0.5f);
    }

    // ---------------- per-cell derived values -------------------------------
    float sxv  = 1.0f / (1.0f + __expf(-a0));
    float syv  = 1.0f / (1.0f + __expf(-a1));
    float conf = 1.0f / (1.0f + __expf(-a6));

    float pw = __expf(a2) * c_aw[a];
    float pl = __expf(a3) * c_al[a];
    float px = sxv + (float)i;
    float py = syv + (float)j;

    float x1 = px - pw * 0.5f, x2 = px + pw * 0.5f;
    float y1s = 1.6f * (py - pl * 0.5f), y2s = 1.6f * (py + pl * 0.5f);
    float parea = pw * pl;
    float th = 0.6f * parea;

    // ---------------- per-warp x/y culling bitmask --------------------------
    // Warp spans cols [colLo, colLo+16), rows [rowLo, rowLo+2).
    const int nc = s_cnt;
    const float colLo = (float)(xT << 4);
    const float rowLo = (float)(rowbase + (yT << 1));
    unsigned mk0, mk1;
    {
        bool p0 = false, p1 = false;
        if (lane < nc) {
            float2 xw = sxw[lane];
            float2 yw = syw[lane];
            p0 = (xw.y > colLo) && (xw.x < colLo + 16.0f)
              && (yw.y > rowLo) && (yw.x < rowLo + 2.0f);
        }
        int l2 = lane + 32;
        if (l2 < nc) {
            float2 xw = sxw[l2];
            float2 yw = syw[l2];
            p1 = (xw.y > colLo) && (xw.x < colLo + 16.0f)
              && (yw.y > rowLo) && (yw.x < rowLo + 2.0f);
        }
        mk0 = __ballot_sync(0xffffffffu, p0);
        mk1 = __ballot_sync(0xffffffffu, p1);
    }

    // ---------------- exists(iou > 0.6) over bitmask survivors --------------
    float m0 = -1e30f;
    unsigned m = mk0;
    int basebit = 0;
#pragma unroll 2
    for (int half = 0; half < 2; half++) {
        while (m) {
            int t = basebit + __ffs(m) - 1;
            m &= m - 1;
            float4 q = cbox[t];
            float  n = cna[t];
            float cw = fminf(x2, q.z) - fmaxf(x1, q.x);
            float ch = fminf(y2s, q.w) - fmaxf(y1s, q.y);
            m0 = fmaxf(m0, fmaf(fmaxf(cw, 0.0f), ch, n));
        }
        m = mk1;
        basebit = 32;
    }
    bool found = m0 > th;

    __syncthreads();                               // sync 3: std_ visible
    const int map = s_map[off0];

    float acc;
    if (map >= 0) {
        acc = matched_loss(map, base, sxv, syv, conf, a2, a3,
                           x1, x2, y1s, y2s, parea);
    } else {
        float cc = found ? 0.0f : conf;
        acc = cc * cc;
    }

    // ---------------- reduction (shuffle-based) -----------------------------
    float v = acc;
#pragma unroll
    for (int o = 16; o > 0; o >>= 1) v += __shfl_down_sync(0xffffffffu, v, o);
    if (lane == 0) wred[wrp] = v;
    __syncthreads();
    if (tid < 32) {
        float s = (tid < 16) ? wred[tid] : 0.0f;
#pragma unroll
        for (int o = 8; o > 0; o >>= 1) s += __shfl_down_sync(0xffffffffu, s, o);
        if (tid == 0) {
            g_partials[bid] = s;
            __threadfence();
            unsigned int r = atomicAdd(&g_count, 1u);
            s_last = (r == (unsigned)(kGrid - 1));
        }
    }
    __syncthreads();

    if (s_last) {
        float s = 0.0f;
        for (int p = tid; p < kGrid; p += kThreads) s += __ldcg(&g_partials[p]);
#pragma unroll
        for (int o = 16; o > 0; o >>= 1) s += __shfl_down_sync(0xffffffffu, s, o);
        if (lane == 0) wred[wrp] = s;
        __syncthreads();
        if (tid == 0) {
            float tot = 0.0f;
#pragma unroll
            for (int q = 0; q < 16; q++) tot += wred[q];
            loss[0] = tot;
            g_count = 0;
        }
        for (int p = 1 + tid; p < out_size; p += kThreads) loss[p] = 0.0f;
    }
}

extern "C" void kernel_launch(void* const* d_in, const int* in_sizes, int n_in,
                              void* d_out, int out_size) {
    const float* output = (const float*)d_in[0];
    const float* target = (const float*)d_in[1];
    k_fused<<<kGrid, kThreads>>>(output, target, (float*)d_out, out_size);
}

// round 14
// speedup vs baseline: 1.1800x; 1.1800x over previous
#include <cuda_runtime.h>

constexpr int kB = 32;
constexpr int kA = 5;
constexpr int kC = 8;
constexpr int kH = 32;
constexpr int kW = 64;
constexpr int kT = 50;
constexpr int kCh = 7 + kC;                 // 15
constexpr int kHW = kH * kW;                // 2048
constexpr int kCellsPerBlock = 512;         // 2 cells/thread (x-pairs): one anchor x 8 rows
constexpr int kBlocksPerB = 20;             // 10240 / 512
constexpr int kGrid = kB * kBlocksPerB;     // 640

__constant__ float c_aw[kA] = {1.08f, 3.42f, 6.63f, 9.42f, 16.62f};
__constant__ float c_al[kA] = {1.19f, 4.41f, 11.38f, 5.11f, 10.52f};

__device__ float        g_partials[kGrid];
__device__ unsigned int g_count = 0;   // self-resets -> graph-replay deterministic

__shared__ float4   cbox[kT];          // {x1, 1.6*y1, x2, 1.6*y2}
__shared__ float    cna[kT];           // -0.6 * target area
__shared__ float2   sxw[kT];           // x-window {txc - tw/3 - eps, txc + tw/3 + eps}
__shared__ float2   syw[kT];           // y-window {tyc - tl/3 - eps, tyc + tl/3 + eps}
__shared__ float    std_[kT][12];      // tx,ty,tw,tl,tim,tre,tcls, x1,y1s,x2,y2s
__shared__ int      s_map[kCellsPerBlock];
__shared__ unsigned s_mask[2];
__shared__ int      s_cnt;
__shared__ float    wred[8];
__shared__ bool     s_last;

__device__ __forceinline__ float fsig(float x) {
    return __fdividef(1.0f, 1.0f + __expf(-x));   // MUFU.EX2 + MUFU.RCP + FMUL
}

// matched-cell loss (rare: <=50 cells/batch)
__device__ __forceinline__ float matched_loss(
    int map, const float* __restrict__ base,
    float sxv, float syv, float conf, float c2, float c3,
    float x1, float x2, float y1s, float y2s, float parea)
{
    float c4 = base[4 * kHW];
    float c5 = base[5 * kHW];
    float dx   = sxv - std_[map][0];
    float dy   = syv - std_[map][1];
    float dw   = c2  - std_[map][2];
    float dl   = c3  - std_[map][3];
    float dim_ = c4  - std_[map][4];
    float dre  = c5  - std_[map][5];

    float bx1 = std_[map][7], by1s = std_[map][8];
    float bx2 = std_[map][9], by2s = std_[map][10];
    float cw  = fminf(x2, bx2) - fmaxf(x1, bx1);
    float chs = fminf(y2s, by2s) - fmaxf(y1s, by1s);
    float inter = fmaxf(cw, 0.0f) * fmaxf(chs, 0.0f) * 0.625f;
    float tgw = bx2 - bx1;
    float tgl = (by2s - by1s) * 0.625f;
    float uni = parea + tgw * tgl - inter;
    float tconf = __fdividef(inter, uni);
    float dconf = conf * 10.0f - tconf * 10.0f;

    float cl[kC];
#pragma unroll
    for (int q = 0; q < kC; q++) cl[q] = base[(size_t)(7 + q) * kHW];
    float mx = cl[0];
#pragma unroll
    for (int q = 1; q < kC; q++) mx = fmaxf(mx, cl[q]);
    float s = 0.0f;
#pragma unroll
    for (int q = 0; q < kC; q++) s += __expf(cl[q] - mx);
    int tcls = (int)std_[map][6];
    float ce = mx + logf(s) - cl[tcls];

    return dx * dx + dy * dy + dw * dw + dl * dl + dim_ * dim_ + dre * dre
         + dconf * dconf + ce;
}

__global__ void __launch_bounds__(256, 6) k_fused(const float* __restrict__ out,
                                                  const float* __restrict__ tgt,
                                                  float* __restrict__ loss,
                                                  int out_size) {
    const int tid = threadIdx.x;
    const int bid = blockIdx.x;
    const int b   = bid / kBlocksPerB;
    const int cb  = bid - b * kBlocksPerB;
    const int a   = cb >> 2;                       // anchor
    const int g8  = cb & 3;                        // 8-row group
    const int cellbase = cb * kCellsPerBlock;

    // warp tiling: 16 cols x 4 contiguous rows; thread = x-pair (i, i+1)
    const int lane = tid & 31;
    const int wrp  = tid >> 5;
    const int xT   = wrp & 3;
    const int yT   = wrp >> 2;                     // 0..1
    const int i0   = (xT << 4) + ((lane & 7) << 1);
    const int rowLocal = (yT << 2) + (lane >> 3);  // 0..7
    const int j    = (g8 << 3) + rowLocal;
    const int off0 = (rowLocal << 6) + i0;         // s_map index (slot1 = +1)
    const int rem0 = (j << 6) + i0;                // even -> float2-aligned

    // hot channels as float2 (cells i0, i0+1); 32-bit offset math
    const int baseOff = ((b * kA + a) * kCh) * kHW + rem0;
    const float* base0 = out + baseOff;
    float2 v0 = *reinterpret_cast<const float2*>(base0 + 0 * kHW);
    float2 v1 = *reinterpret_cast<const float2*>(base0 + 1 * kHW);
    float2 v2 = *reinterpret_cast<const float2*>(base0 + 2 * kHW);
    float2 v3 = *reinterpret_cast<const float2*>(base0 + 3 * kHW);
    float2 v6 = *reinterpret_cast<const float2*>(base0 + 6 * kHW);

    // ---------------- phase 1: per-target values + masks --------------------
    s_map[tid] = -1;
    s_map[tid + 256] = -1;
    if (tid == 0) s_cnt = 0;

    const float* tr = tgt + (b * kT + tid) * 7;
    bool validt = (tid < kT) && (tr[1] != 0.0f);
    unsigned bm = __ballot_sync(0xffffffffu, validt);
    if ((tid & 31) == 0 && tid < 64) s_mask[tid >> 5] = bm;

    float gx = 0.f, gy = 0.f, gw = 0.f, gl = 0.f, garea = 0.f;
    int gi = 0, gj = 0, besta = 0, off = -1;
    if (validt) {
        gx = tr[1] * (float)kW;
        gy = tr[2] * (float)kH;
        gw = tr[3] * (float)kW;
        gl = tr[4] * (float)kH;
        gi = min(max((int)gx, 0), kW - 1);
        gj = min(max((int)gy, 0), kH - 1);
        garea = gw * gl;

        // division-free first-max-wins anchor argmax
        float bin = fminf(gw, c_aw[0]) * fminf(gl, c_al[0]);
        float bun = garea + c_aw[0] * c_al[0] - bin;
#pragma unroll
        for (int q = 1; q < kA; q++) {
            float in_ = fminf(gw, c_aw[q]) * fminf(gl, c_al[q]);
            float un_ = garea + c_aw[q] * c_al[q] - in_;
            if (in_ * bun > bin * un_) { besta = q; bin = in_; bun = un_; }
        }
        off = ((besta * kH + gj) * kW + gi) - cellbase;
    }
    __syncthreads();                               // sync 1

    unsigned long long mm = (unsigned long long)s_mask[0]
                          | ((unsigned long long)s_mask[1] << 32);
    const int nv = __ffsll((long long)~mm) - 1;    // cumprod-validity prefix

    const bool inpfx = (tid < nv);
    if (inpfx) {
        if (off >= 0 && off < kCellsPerBlock) atomicMax(&s_map[off], tid);
        // block-level y-cull over 8 rows: IoU>0.6 needs |pyc-tyc| < tl/3
        float tl3 = gl * (1.0f / 3.0f) + 1e-3f;
        float jlo = (float)(8 * g8);
        if (gy + tl3 > jlo && gy - tl3 < jlo + 8.0f) {
            int p = atomicAdd(&s_cnt, 1);
            cbox[p] = make_float4(gx - gw * 0.5f, 1.6f * (gy - gl * 0.5f),
                                  gx + gw * 0.5f, 1.6f * (gy + gl * 0.5f));
            cna[p]  = -0.6f * garea;
            float tw3 = gw * (1.0f / 3.0f) + 1e-3f;
            sxw[p] = make_float2(gx - tw3, gx + tw3);
            syw[p] = make_float2(gy - tl3, gy + tl3);
        }
    }
    __syncthreads();                               // sync 2

    // phase 2: dedupe winners write regression targets (hidden behind loop)
    if (inpfx && off >= 0 && off < kCellsPerBlock && s_map[off] == tid) {
        std_[tid][0] = gx - (float)gi;
        std_[tid][1] = gy - (float)gj;
        std_[tid][2] = logf(gw / c_aw[besta]);
        std_[tid][3] = logf(gl / c_al[besta]);
        std_[tid][4] = tr[5];
        std_[tid][5] = tr[6];
        std_[tid][6] = tr[0];
        std_[tid][7] = gx - gw * 0.5f;
        std_[tid][8] = 1.6f * (gy - gl * 0.5f);
        std_[tid][9] = gx + gw * 0.5f;
        std_[tid][10] = 1.6f * (gy + gl * 0.5f);
    }

    // ---------------- per-cell derived values -------------------------------
    float sxv0  = fsig(v0.x);
    float syv0  = fsig(v1.x);
    float conf0 = fsig(v6.x);
    float sxv1  = fsig(v0.y);
    float syv1  = fsig(v1.y);
    float conf1 = fsig(v6.y);

    float pw0 = __expf(v2.x) * c_aw[a];
    float pl0 = __expf(v3.x) * c_al[a];
    float pw1 = __expf(v2.y) * c_aw[a];
    float pl1 = __expf(v3.y) * c_al[a];

    float px0 = sxv0 + (float)i0,       py0 = syv0 + (float)j;
    float px1 = sxv1 + (float)(i0 + 1), py1 = syv1 + (float)j;

    float X1a = px0 - pw0 * 0.5f, X2a = px0 + pw0 * 0.5f;
    float Y1a = 1.6f * (py0 - pl0 * 0.5f), Y2a = 1.6f * (py0 + pl0 * 0.5f);
    float X1b = px1 - pw1 * 0.5f, X2b = px1 + pw1 * 0.5f;
    float Y1b = 1.6f * (py1 - pl1 * 0.5f), Y2b = 1.6f * (py1 + pl1 * 0.5f);

    float parea0 = pw0 * pl0, parea1 = pw1 * pl1;
    float th0 = 0.6f * parea0, th1 = 0.6f * parea1;

    // ---------------- per-warp x/y culling bitmask --------------------------
    // Warp spans cols [16xT, 16xT+16), rows [rowLo, rowLo+4).
    const int nc = s_cnt;
    const float colLo = (float)(xT << 4);
    const float rowLo = (float)((g8 << 3) + (yT << 2));
    unsigned mk0, mk1;
    {
        bool p0 = false, p1 = false;
        if (lane < nc) {
            float2 xw = sxw[lane];
            float2 yw = syw[lane];
            p0 = (xw.y > colLo) && (xw.x < colLo + 16.0f)
              && (yw.y > rowLo) && (yw.x < rowLo + 4.0f);
        }
        int l2 = lane + 32;
        if (l2 < nc) {
            float2 xw = sxw[l2];
            float2 yw = syw[l2];
            p1 = (xw.y > colLo) && (xw.x < colLo + 16.0f)
              && (yw.y > rowLo) && (yw.x < rowLo + 4.0f);
        }
        mk0 = __ballot_sync(0xffffffffu, p0);
        mk1 = __ballot_sync(0xffffffffu, p1);
    }

    // ---------------- exists(iou > 0.6) over bitmask survivors --------------
    float m0 = -1e30f, m1 = -1e30f;
    unsigned m = mk0;
    int basebit = 0;
#pragma unroll 2
    for (int half = 0; half < 2; half++) {
        while (m) {
            int t = basebit + __ffs(m) - 1;
            m &= m - 1;
            float4 q = cbox[t];
            float  n = cna[t];
            float cw0 = fminf(X2a, q.z) - fmaxf(X1a, q.x);
            float ch0 = fminf(Y2a, q.w) - fmaxf(Y1a, q.y);
            m0 = fmaxf(m0, fmaf(fmaxf(cw0, 0.0f), ch0, n));
            float cw1 = fminf(X2b, q.z) - fmaxf(X1b, q.x);
            float ch1 = fminf(Y2b, q.w) - fmaxf(Y1b, q.y);
            m1 = fmaxf(m1, fmaf(fmaxf(cw1, 0.0f), ch1, n));
        }
        m = mk1;
        basebit = 32;
    }
    bool found0 = m0 > th0;
    bool found1 = m1 > th1;

    __syncthreads();                               // sync 3: std_ visible
    const int map0 = s_map[off0];
    const int map1 = s_map[off0 + 1];

    float acc0, acc1;
    if (map0 >= 0) {
        acc0 = matched_loss(map0, base0, sxv0, syv0, conf0, v2.x, v3.x,
                            X1a, X2a, Y1a, Y2a, parea0);
    } else {
        float cc = found0 ? 0.0f : conf0;
        acc0 = cc * cc;
    }
    if (map1 >= 0) {
        acc1 = matched_loss(map1, base0 + 1, sxv1, syv1, conf1, v2.y, v3.y,
                            X1b, X2b, Y1b, Y2b, parea1);
    } else {
        float cc = found1 ? 0.0f : conf1;
        acc1 = cc * cc;
    }

    // ---------------- reduction (shuffle-based) -----------------------------
    float v = acc0 + acc1;
#pragma unroll
    for (int o = 16; o > 0; o >>= 1) v += __shfl_down_sync(0xffffffffu, v, o);
    if (lane == 0) wred[wrp] = v;
    __syncthreads();
    if (tid < 32) {
        float s = (tid < 8) ? wred[tid] : 0.0f;
#pragma unroll
        for (int o = 4; o > 0; o >>= 1) s += __shfl_down_sync(0xffffffffu, s, o);
        if (tid == 0) {
            g_partials[bid] = s;
            __threadfence();
            unsigned int r = atomicAdd(&g_count, 1u);
            s_last = (r == (unsigned)(kGrid - 1));
        }
    }
    __syncthreads();

    if (s_last) {
        float s = 0.0f;
        for (int p = tid; p < kGrid; p += 256) s += __ldcg(&g_partials[p]);
#pragma unroll
        for (int o = 16; o > 0; o >>= 1) s += __shfl_down_sync(0xffffffffu, s, o);
        if (lane == 0) wred[wrp] = s;
        __syncthreads();
        if (tid == 0) {
            float tot = 0.0f;
#pragma unroll
            for (int q = 0; q < 8; q++) tot += wred[q];
            loss[0] = tot;
            g_count = 0;
        }
        for (int p = 1 + tid; p < out_size; p += 256) loss[p] = 0.0f;
    }
}

extern "C" void kernel_launch(void* const* d_in, const int* in_sizes, int n_in,
                              void* d_out, int out_size) {
    const float* output = (const float*)d_in[0];
    const float* target = (const float*)d_in[1];
    k_fused<<<kGrid, 256>>>(output, target, (float*)d_out, out_size);
}